// round 2
// baseline (speedup 1.0000x reference)
#include <cuda_runtime.h>
#include <math.h>

#define Bsz 4
#define Lseq 4096
#define DIN 256
#define DST 16
#define DTR 8

// ---------------- scratch (module-static device memory; no allocations) ----------------
__device__ __align__(16) float g_fop[Bsz*Lseq*128];      // (b,l,128)
__device__ __align__(16) float g_xz [Bsz*Lseq*512];      // (b,l,512)
__device__ __align__(16) float g_x  [Bsz*DIN*Lseq];      // post-conv silu, (b,d,l)
__device__ __align__(16) float g_z  [Bsz*DIN*Lseq];      // (b,d,l)
__device__ __align__(16) float g_dt [Bsz*DIN*Lseq];      // (b,d,l)
__device__ __align__(16) float g_dtr[Bsz*Lseq*DTR];      // (b,l,8)
__device__ __align__(16) float g_Bm [Bsz*Lseq*DST];      // (b,l,16)
__device__ __align__(16) float g_Cm [Bsz*Lseq*DST];      // (b,l,16)
__device__ __align__(16) float g_y  [Bsz*Lseq*DIN];      // (b,l,d)
__device__ __align__(16) float g_res_seq[Bsz*Lseq*32];   // (b,l,c)
__device__ __align__(16) float g_residual[Bsz*32*Lseq];  // (b,c,h,w)
__device__ __align__(16) float g_wsum[32*DIN];
__device__ float g_cmean[Bsz*32];
__device__ float g_scale[Bsz*32];

__device__ __forceinline__ float silu_f(float v) { return v / (1.f + __expf(-v)); }
__device__ __forceinline__ float softplus_f(float v) { return (v > 20.f) ? v : log1pf(expf(v)); }

// ---------------- K0: gather 4-direction sequence from fo1 ----------------
__global__ void gather_kernel(const float* __restrict__ fo1) {
    int idx = blockIdx.x * 256 + threadIdx.x;            // < 4*4096*128
    int j = idx & 127;
    int l = (idx >> 7) & 4095;
    int b = idx >> 19;
    int g = j >> 5, c = j & 31;
    int l2 = (g & 1) ? (4095 - l) : l;
    int pos = (g < 2) ? l2 : (((l2 & 63) << 6) | (l2 >> 6));
    g_fop[idx] = fo1[((size_t)(b*32 + c))*4096 + pos];
}

// ---------------- generic fp32 tiled GEMM body: C[M,N] = A[M,K] * W[N,K]^T ----------------
template<int BM, int BN, int BK, int TM, int TN>
__device__ __forceinline__ void gemm_body(const float* __restrict__ A, const float* __restrict__ W,
                                          float* __restrict__ C, int M, int N, int K) {
    __shared__ float As[BK][BM + 4];
    __shared__ float Ws[BK][BN + 4];
    const int tid = threadIdx.x;                         // (BM/TM)*(BN/TN) == 256
    const int colT = BN / TN;
    const int tm = (tid / colT) * TM;
    const int tn = (tid % colT) * TN;
    const int bm = blockIdx.y * BM;
    const int bn = blockIdx.x * BN;
    float acc[TM][TN];
    #pragma unroll
    for (int i = 0; i < TM; i++)
        #pragma unroll
        for (int j = 0; j < TN; j++) acc[i][j] = 0.f;

    for (int k0 = 0; k0 < K; k0 += BK) {
        for (int i = tid; i < BM*BK; i += 256) {
            int m = i / BK, k = i % BK;
            As[k][m] = A[(size_t)(bm + m)*K + k0 + k];
        }
        for (int i = tid; i < BN*BK; i += 256) {
            int n = i / BK, k = i % BK;
            Ws[k][n] = W[(size_t)(bn + n)*K + k0 + k];
        }
        __syncthreads();
        #pragma unroll
        for (int k = 0; k < BK; k++) {
            float ra[TM], rw[TN];
            #pragma unroll
            for (int i = 0; i < TM; i++) ra[i] = As[k][tm + i];
            #pragma unroll
            for (int j = 0; j < TN; j++) rw[j] = Ws[k][tn + j];
            #pragma unroll
            for (int i = 0; i < TM; i++)
                #pragma unroll
                for (int j = 0; j < TN; j++) acc[i][j] = fmaf(ra[i], rw[j], acc[i][j]);
        }
        __syncthreads();
    }
    #pragma unroll
    for (int i = 0; i < TM; i++)
        #pragma unroll
        for (int j = 0; j < TN; j++)
            C[(size_t)(bm + tm + i)*N + bn + tn + j] = acc[i][j];
}

// K1: xz = fop @ in_w^T   — globals referenced device-side (host must not touch them)
__global__ void gemm1_kernel(const float* __restrict__ in_w) {
    gemm_body<64,64,32,4,4>(g_fop, in_w, g_xz, 16384, 512, 128);
}
// K7: res_seq = y @ wsum^T
__global__ void gemm3_kernel() {
    gemm_body<64,32,32,4,2>(g_y, g_wsum, g_res_seq, 16384, 32, 256);
}

// ---------------- K2: causal depthwise conv(4)+bias+silu for x, transpose both x,z ----------------
__global__ void conv_transpose_kernel(const float* __restrict__ conv_w, const float* __restrict__ conv_b) {
    // grid: (ctile 16, ltile 128, b 4), block 256
    int b = blockIdx.z, lt = blockIdx.y, ct = blockIdx.x;
    int c0 = ct * 32;
    int l0 = lt * 32;
    __shared__ float s[35][33];
    for (int i = threadIdx.x; i < 35*32; i += 256) {
        int li = i >> 5, ci = i & 31;
        int l = l0 - 3 + li;
        s[li][ci] = (l >= 0) ? g_xz[((size_t)b*4096 + l)*512 + c0 + ci] : 0.f;
    }
    __syncthreads();
    int li = threadIdx.x & 31;
    int cw0 = threadIdx.x >> 5;       // 8 slices
    if (c0 < 256) {
        for (int ci = cw0; ci < 32; ci += 8) {
            int c = c0 + ci;
            float w0 = conv_w[c*4+0], w1 = conv_w[c*4+1], w2 = conv_w[c*4+2], w3 = conv_w[c*4+3];
            float acc = conv_b[c];
            acc = fmaf(w0, s[li][ci], acc);
            acc = fmaf(w1, s[li+1][ci], acc);
            acc = fmaf(w2, s[li+2][ci], acc);
            acc = fmaf(w3, s[li+3][ci], acc);
            g_x[((size_t)(b*256 + c))*4096 + l0 + li] = silu_f(acc);
        }
    } else {
        for (int ci = cw0; ci < 32; ci += 8) {
            int zc = c0 + ci - 256;
            g_z[((size_t)(b*256 + zc))*4096 + l0 + li] = s[li+3][ci];
        }
    }
}

// ---------------- K3: dbl = x @ x_w^T (K=256, N=40), split into dtr/B/C ----------------
__global__ void gemm2_kernel(const float* __restrict__ x_w) {
    int b = blockIdx.x >> 5, lt = blockIdx.x & 31;
    int l0 = lt * 128;
    __shared__ float xs[16][128];
    __shared__ float ws[40][17];
    int tid = threadIdx.x;
    int ll = tid & 127, jg = tid >> 7;
    float acc[20];
    #pragma unroll
    for (int j = 0; j < 20; j++) acc[j] = 0.f;

    for (int k0 = 0; k0 < 256; k0 += 16) {
        for (int i = tid; i < 16*128; i += 256) {
            int di = i >> 7, lix = i & 127;
            xs[di][lix] = g_x[((size_t)(b*256 + k0 + di))*4096 + l0 + lix];
        }
        for (int i = tid; i < 40*16; i += 256) {
            int j = i / 16, kk = i % 16;
            ws[j][kk] = x_w[j*256 + k0 + kk];
        }
        __syncthreads();
        #pragma unroll
        for (int di = 0; di < 16; di++) {
            float a = xs[di][ll];
            #pragma unroll
            for (int jj = 0; jj < 20; jj++)
                acc[jj] = fmaf(a, ws[jg*20 + jj][di], acc[jj]);
        }
        __syncthreads();
    }
    int l = l0 + ll;
    #pragma unroll
    for (int jj = 0; jj < 20; jj++) {
        int j = jg*20 + jj;
        float v = acc[jj];
        if (j < 8)       g_dtr[((size_t)b*4096 + l)*8  + j]       = v;
        else if (j < 24) g_Bm [((size_t)b*4096 + l)*16 + (j - 8)] = v;
        else             g_Cm [((size_t)b*4096 + l)*16 + (j - 24)] = v;
    }
}

// ---------------- K4: dt = softplus(dtr @ dt_w^T + dt_b), layout (b,d,l) ----------------
__global__ void dtproj_kernel(const float* __restrict__ dt_w, const float* __restrict__ dt_b) {
    int bid = blockIdx.x;             // 4*256*16
    int lc = bid & 15;
    int d  = (bid >> 4) & 255;
    int b  = bid >> 12;
    int l0 = lc * 256;
    __shared__ float s[8][264];
    for (int i = threadIdx.x; i < 2048; i += 256) {
        float v = g_dtr[((size_t)b*4096 + l0)*8 + i];
        s[i & 7][i >> 3] = v;
    }
    __syncthreads();
    float acc = dt_b[d];
    #pragma unroll
    for (int r = 0; r < 8; r++) acc = fmaf(s[r][threadIdx.x], dt_w[d*8 + r], acc);
    g_dt[((size_t)(b*256 + d))*4096 + l0 + threadIdx.x] = softplus_f(acc);
}

// ---------------- K5: selective scan + skip + gate.  1 warp = 2 (b,d) chains ----------------
__global__ void scan_kernel(const float* __restrict__ A_log, const float* __restrict__ Dp) {
    int lane = threadIdx.x;
    int half = lane >> 4, n = lane & 15;
    int g = blockIdx.x * 2 + half;     // 0..1023
    int b = g >> 8, d = g & 255;
    const float* dtp = g_dt + (size_t)(b*256 + d)*4096;
    const float* xp  = g_x  + (size_t)(b*256 + d)*4096;
    const float* zp  = g_z  + (size_t)(b*256 + d)*4096;
    const float* Bp  = g_Bm + (size_t)b*4096*16 + n;
    const float* Cp  = g_Cm + (size_t)b*4096*16 + n;
    float An = -__expf(A_log[d*16 + n]);
    float Dd = Dp[d];
    float* yout = g_y + (size_t)b*4096*256 + d;
    float h = 0.f;
    for (int l = 0; l < 4096; l += 4) {
        float4 dt4 = *(const float4*)(dtp + l);
        float4 x4  = *(const float4*)(xp  + l);
        float4 z4  = *(const float4*)(zp  + l);
        float dta[4] = {dt4.x, dt4.y, dt4.z, dt4.w};
        float xa [4] = {x4.x,  x4.y,  x4.z,  x4.w};
        float za [4] = {z4.x,  z4.y,  z4.z,  z4.w};
        #pragma unroll
        for (int i = 0; i < 4; i++) {
            float dt = dta[i];
            float Bv = Bp[(l + i)*16];
            float Cv = Cp[(l + i)*16];
            float dA = __expf(dt * An);
            h = fmaf(dA, h, dt * xa[i] * Bv);
            float y = h * Cv;
            y += __shfl_xor_sync(0xFFFFFFFFu, y, 8);
            y += __shfl_xor_sync(0xFFFFFFFFu, y, 4);
            y += __shfl_xor_sync(0xFFFFFFFFu, y, 2);
            y += __shfl_xor_sync(0xFFFFFFFFu, y, 1);
            if (n == 0) {
                float zz = za[i];
                float gate = zz / (1.f + __expf(-zz));
                yout[(size_t)(l + i)*256] = fmaf(xa[i], Dd, y) * gate;
            }
        }
    }
}

// ---------------- K6: collapse out_w group-sum ----------------
__global__ void wsum_kernel(const float* __restrict__ out_w) {
    int i = blockIdx.x * 256 + threadIdx.x;  // 8192
    int c = i >> 8, d = i & 255;
    g_wsum[c*256 + d] = out_w[(c)*256 + d] + out_w[(32 + c)*256 + d]
                      + out_w[(64 + c)*256 + d] + out_w[(96 + c)*256 + d];
}

// ---------------- K8: residual = res_seq^T * fo2, and per-(b,c) sum ----------------
__global__ void residual_kernel(const float* __restrict__ fo2) {
    int b = blockIdx.x >> 5, c = blockIdx.x & 31;
    float partial = 0.f;
    for (int l = threadIdx.x; l < 4096; l += 256) {
        float r = g_res_seq[((size_t)b*4096 + l)*32 + c] * fo2[((size_t)(b*32 + c))*4096 + l];
        g_residual[((size_t)(b*32 + c))*4096 + l] = r;
        partial += r;
    }
    __shared__ float red[256];
    red[threadIdx.x] = partial;
    __syncthreads();
    for (int st = 128; st > 0; st >>= 1) {
        if (threadIdx.x < st) red[threadIdx.x] += red[threadIdx.x + st];
        __syncthreads();
    }
    if (threadIdx.x == 0) g_cmean[b*32 + c] = red[0];
}

// ---------------- K9: the entire tiny mamba2, one block ----------------
__global__ void mamba2_kernel(const float* __restrict__ in_w, const float* __restrict__ conv_w,
                              const float* __restrict__ conv_b, const float* __restrict__ x_w,
                              const float* __restrict__ dt_w, const float* __restrict__ dt_b,
                              const float* __restrict__ A_log, const float* __restrict__ Dp,
                              const float* __restrict__ out_w) {
    __shared__ float sxp[4][32][4];
    __shared__ float sx [4][32][4];
    __shared__ float sz [4][32][4];
    __shared__ float sdt[4][32][4];
    __shared__ float sB [4][32][16];
    __shared__ float sC [4][32][16];
    __shared__ float sy [4][32][4];
    int tid = threadIdx.x;            // 128
    int b = tid >> 5, l = tid & 31;
    float m0 = g_cmean[b*32 + l] * (1.f/4096.f);
    float m1 = g_cmean[b*32 + 31 - l] * (1.f/4096.f);
    #pragma unroll
    for (int j = 0; j < 4; j++) {
        sxp[b][l][j] = m0*in_w[j*2]       + m1*in_w[j*2 + 1];
        sz [b][l][j] = m0*in_w[(j+4)*2]   + m1*in_w[(j+4)*2 + 1];
    }
    __syncthreads();
    #pragma unroll
    for (int c = 0; c < 4; c++) {
        float acc = conv_b[c];
        #pragma unroll
        for (int t = 0; t < 4; t++) {
            int ls = l - 3 + t;
            float v = (ls >= 0) ? sxp[b][ls][c] : 0.f;
            acc = fmaf(conv_w[c*4 + t], v, acc);
        }
        sx[b][l][c] = acc / (1.f + expf(-acc));
    }
    __syncthreads();
    {
        float xv[4] = {sx[b][l][0], sx[b][l][1], sx[b][l][2], sx[b][l][3]};
        float dtr = 0.f;
        #pragma unroll
        for (int c = 0; c < 4; c++) dtr = fmaf(xv[c], x_w[c], dtr);
        #pragma unroll
        for (int n = 0; n < 16; n++) {
            float bb = 0.f, cc = 0.f;
            #pragma unroll
            for (int c = 0; c < 4; c++) {
                bb = fmaf(xv[c], x_w[(1 + n)*4 + c], bb);
                cc = fmaf(xv[c], x_w[(17 + n)*4 + c], cc);
            }
            sB[b][l][n] = bb;
            sC[b][l][n] = cc;
        }
        #pragma unroll
        for (int dd = 0; dd < 4; dd++) {
            float a = fmaf(dtr, dt_w[dd], dt_b[dd]);
            sdt[b][l][dd] = softplus_f(a);
        }
    }
    __syncthreads();
    {
        int lane = tid & 31, wb = tid >> 5;
        int grp = lane >> 4, n = lane & 15;
        int d0 = grp, d1 = grp + 2;
        float A0 = -expf(A_log[d0*16 + n]);
        float A1 = -expf(A_log[d1*16 + n]);
        float h0 = 0.f, h1 = 0.f;
        for (int t = 0; t < 32; t++) {
            float Bv = sB[wb][t][n], Cv = sC[wb][t][n];
            float dt0 = sdt[wb][t][d0], x0 = sx[wb][t][d0];
            float dt1 = sdt[wb][t][d1], x1 = sx[wb][t][d1];
            h0 = fmaf(__expf(dt0*A0), h0, dt0*x0*Bv);
            h1 = fmaf(__expf(dt1*A1), h1, dt1*x1*Bv);
            float y0 = h0*Cv, y1 = h1*Cv;
            y0 += __shfl_xor_sync(0xFFFFFFFFu, y0, 8);
            y0 += __shfl_xor_sync(0xFFFFFFFFu, y0, 4);
            y0 += __shfl_xor_sync(0xFFFFFFFFu, y0, 2);
            y0 += __shfl_xor_sync(0xFFFFFFFFu, y0, 1);
            y1 += __shfl_xor_sync(0xFFFFFFFFu, y1, 8);
            y1 += __shfl_xor_sync(0xFFFFFFFFu, y1, 4);
            y1 += __shfl_xor_sync(0xFFFFFFFFu, y1, 2);
            y1 += __shfl_xor_sync(0xFFFFFFFFu, y1, 1);
            if (n == 0) { sy[wb][t][d0] = y0; sy[wb][t][d1] = y1; }
        }
    }
    __syncthreads();
    {
        float scale = 0.f;
        #pragma unroll
        for (int dd = 0; dd < 4; dd++) {
            float yv = fmaf(sx[b][l][dd], Dp[dd], sy[b][l][dd]);
            float zz = sz[b][l][dd];
            yv *= zz / (1.f + expf(-zz));
            scale = fmaf(yv, out_w[dd] + out_w[4 + dd], scale);
        }
        g_scale[b*32 + l] = scale;
    }
}

// ---------------- K10: out = residual * (scale + 1) ----------------
__global__ void final_kernel(float* __restrict__ out) {
    int idx = blockIdx.x * 256 + threadIdx.x;  // 524288
    out[idx] = g_residual[idx] * (g_scale[idx >> 12] + 1.f);
}

// ---------------- launch ----------------
extern "C" void kernel_launch(void* const* d_in, const int* in_sizes, int n_in,
                              void* d_out, int out_size) {
    const float* fo1      = (const float*)d_in[0];
    const float* fo2      = (const float*)d_in[1];
    const float* m1_in_w  = (const float*)d_in[2];
    const float* m1_conv_w= (const float*)d_in[3];
    const float* m1_conv_b= (const float*)d_in[4];
    const float* m1_x_w   = (const float*)d_in[5];
    const float* m1_dt_w  = (const float*)d_in[6];
    const float* m1_dt_b  = (const float*)d_in[7];
    const float* m1_A_log = (const float*)d_in[8];
    const float* m1_D     = (const float*)d_in[9];
    const float* m1_out_w = (const float*)d_in[10];
    const float* m2_in_w  = (const float*)d_in[11];
    const float* m2_conv_w= (const float*)d_in[12];
    const float* m2_conv_b= (const float*)d_in[13];
    const float* m2_x_w   = (const float*)d_in[14];
    const float* m2_dt_w  = (const float*)d_in[15];
    const float* m2_dt_b  = (const float*)d_in[16];
    const float* m2_A_log = (const float*)d_in[17];
    const float* m2_D     = (const float*)d_in[18];
    const float* m2_out_w = (const float*)d_in[19];
    float* out = (float*)d_out;

    // fop gather
    gather_kernel<<<8192, 256>>>(fo1);
    // xz = fop @ in_w^T   (16384 x 128) @ (512 x 128)^T
    gemm1_kernel<<<dim3(512/64, 16384/64), 256>>>(m1_in_w);
    // conv + silu + transpose
    conv_transpose_kernel<<<dim3(16, 128, 4), 256>>>(m1_conv_w, m1_conv_b);
    // dbl projection
    gemm2_kernel<<<128, 256>>>(m1_x_w);
    // dt projection
    dtproj_kernel<<<4*256*16, 256>>>(m1_dt_w, m1_dt_b);
    // selective scan
    scan_kernel<<<512, 32>>>(m1_A_log, m1_D);
    // group-summed out projection
    wsum_kernel<<<32, 256>>>(m1_out_w);
    gemm3_kernel<<<dim3(1, 16384/64), 256>>>();
    // residual + channel means
    residual_kernel<<<128, 256>>>(fo2);
    // tiny mamba2
    mamba2_kernel<<<1, 128>>>(m2_in_w, m2_conv_w, m2_conv_b, m2_x_w, m2_dt_w,
                              m2_dt_b, m2_A_log, m2_D, m2_out_w);
    // final scale
    final_kernel<<<2048, 256>>>(out);
}

// round 3
// speedup vs baseline: 3.8968x; 3.8968x over previous
#include <cuda_runtime.h>
#include <math.h>

#define Bsz 4
#define Lseq 4096
#define DIN 256
#define DST 16
#define DTR 8
#define NSEG 16
#define SEGL 256   // Lseq / NSEG

// ---------------- scratch ----------------
__device__ __align__(16) float g_fop[Bsz*Lseq*128];      // (b,l,128)
__device__ __align__(16) float g_xz [Bsz*Lseq*512];      // (b,l,512)
__device__ __align__(16) float g_x  [Bsz*DIN*Lseq];      // post-conv silu, (b,d,l)
__device__ __align__(16) float g_z  [Bsz*DIN*Lseq];      // (b,d,l)
__device__ __align__(16) float g_dt [Bsz*DIN*Lseq];      // (b,d,l)
__device__ __align__(16) float g_dtr[Bsz*Lseq*DTR];      // (b,l,8)
__device__ __align__(16) float g_Bm [Bsz*Lseq*DST];      // (b,l,16)
__device__ __align__(16) float g_Cm [Bsz*Lseq*DST];      // (b,l,16)
__device__ __align__(16) float g_y  [Bsz*DIN*Lseq];      // (b,d,l)  << transposed now
__device__ __align__(16) float g_res_seq[Bsz*Lseq*32];   // (b,l,c)
__device__ __align__(16) float g_residual[Bsz*32*Lseq];  // (b,c,h,w)
__device__ __align__(16) float g_wsum[32*DIN];
__device__ __align__(16) float g_segH[Bsz*DIN*NSEG*DST]; // (chain,s,n) end-state
__device__ __align__(16) float g_segP[Bsz*DIN*NSEG*DST]; // (chain,s,n) decay product
__device__ __align__(16) float g_h0  [Bsz*DIN*NSEG*DST]; // (chain,s,n) seg initial state
__device__ float g_cmean[Bsz*32];
__device__ float g_scale[Bsz*32];

__device__ __forceinline__ float silu_f(float v) { return v / (1.f + __expf(-v)); }
__device__ __forceinline__ float softplus_f(float v) { return (v > 20.f) ? v : log1pf(expf(v)); }

// ---------------- K0: gather 4-direction sequence from fo1 ----------------
__global__ void gather_kernel(const float* __restrict__ fo1) {
    int idx = blockIdx.x * 256 + threadIdx.x;            // < 4*4096*128
    int j = idx & 127;
    int l = (idx >> 7) & 4095;
    int b = idx >> 19;
    int g = j >> 5, c = j & 31;
    int l2 = (g & 1) ? (4095 - l) : l;
    int pos = (g < 2) ? l2 : (((l2 & 63) << 6) | (l2 >> 6));
    g_fop[idx] = fo1[((size_t)(b*32 + c))*4096 + pos];
}

// ---------------- generic fp32 tiled GEMM body: C[M,N] = A[M,K] * W[N,K]^T ----------------
template<int BM, int BN, int BK, int TM, int TN>
__device__ __forceinline__ void gemm_body(const float* __restrict__ A, const float* __restrict__ W,
                                          float* __restrict__ C, int M, int N, int K) {
    __shared__ float As[BK][BM + 4];
    __shared__ float Ws[BK][BN + 4];
    const int tid = threadIdx.x;                         // (BM/TM)*(BN/TN) == 256
    const int colT = BN / TN;
    const int tm = (tid / colT) * TM;
    const int tn = (tid % colT) * TN;
    const int bm = blockIdx.y * BM;
    const int bn = blockIdx.x * BN;
    float acc[TM][TN];
    #pragma unroll
    for (int i = 0; i < TM; i++)
        #pragma unroll
        for (int j = 0; j < TN; j++) acc[i][j] = 0.f;

    for (int k0 = 0; k0 < K; k0 += BK) {
        for (int i = tid; i < BM*BK; i += 256) {
            int m = i / BK, k = i % BK;
            As[k][m] = A[(size_t)(bm + m)*K + k0 + k];
        }
        for (int i = tid; i < BN*BK; i += 256) {
            int n = i / BK, k = i % BK;
            Ws[k][n] = W[(size_t)(bn + n)*K + k0 + k];
        }
        __syncthreads();
        #pragma unroll
        for (int k = 0; k < BK; k++) {
            float ra[TM], rw[TN];
            #pragma unroll
            for (int i = 0; i < TM; i++) ra[i] = As[k][tm + i];
            #pragma unroll
            for (int j = 0; j < TN; j++) rw[j] = Ws[k][tn + j];
            #pragma unroll
            for (int i = 0; i < TM; i++)
                #pragma unroll
                for (int j = 0; j < TN; j++) acc[i][j] = fmaf(ra[i], rw[j], acc[i][j]);
        }
        __syncthreads();
    }
    #pragma unroll
    for (int i = 0; i < TM; i++)
        #pragma unroll
        for (int j = 0; j < TN; j++)
            C[(size_t)(bm + tm + i)*N + bn + tn + j] = acc[i][j];
}

// K1: xz = fop @ in_w^T
__global__ void gemm1_kernel(const float* __restrict__ in_w) {
    gemm_body<128,64,16,8,4>(g_fop, in_w, g_xz, 16384, 512, 128);
}

// ---------------- K2: causal depthwise conv(4)+bias+silu, transpose x,z to (b,d,l) ----------------
__global__ void conv_transpose_kernel(const float* __restrict__ conv_w, const float* __restrict__ conv_b) {
    int b = blockIdx.z, lt = blockIdx.y, ct = blockIdx.x;
    int c0 = ct * 32;
    int l0 = lt * 32;
    __shared__ float s[35][33];
    for (int i = threadIdx.x; i < 35*32; i += 256) {
        int li = i >> 5, ci = i & 31;
        int l = l0 - 3 + li;
        s[li][ci] = (l >= 0) ? g_xz[((size_t)b*4096 + l)*512 + c0 + ci] : 0.f;
    }
    __syncthreads();
    int li = threadIdx.x & 31;
    int cw0 = threadIdx.x >> 5;
    if (c0 < 256) {
        for (int ci = cw0; ci < 32; ci += 8) {
            int c = c0 + ci;
            float w0 = conv_w[c*4+0], w1 = conv_w[c*4+1], w2 = conv_w[c*4+2], w3 = conv_w[c*4+3];
            float acc = conv_b[c];
            acc = fmaf(w0, s[li][ci], acc);
            acc = fmaf(w1, s[li+1][ci], acc);
            acc = fmaf(w2, s[li+2][ci], acc);
            acc = fmaf(w3, s[li+3][ci], acc);
            g_x[((size_t)(b*256 + c))*4096 + l0 + li] = silu_f(acc);
        }
    } else {
        for (int ci = cw0; ci < 32; ci += 8) {
            int zc = c0 + ci - 256;
            g_z[((size_t)(b*256 + zc))*4096 + l0 + li] = s[li+3][ci];
        }
    }
}

// ---------------- K3: dbl = x @ x_w^T (K=256, N=40), split into dtr/B/C ----------------
__global__ void gemm2_kernel(const float* __restrict__ x_w) {
    int b = blockIdx.x >> 5, lt = blockIdx.x & 31;
    int l0 = lt * 128;
    __shared__ float xs[16][128];
    __shared__ float ws[40][17];
    int tid = threadIdx.x;
    int ll = tid & 127, jg = tid >> 7;
    float acc[20];
    #pragma unroll
    for (int j = 0; j < 20; j++) acc[j] = 0.f;

    for (int k0 = 0; k0 < 256; k0 += 16) {
        for (int i = tid; i < 16*128; i += 256) {
            int di = i >> 7, lix = i & 127;
            xs[di][lix] = g_x[((size_t)(b*256 + k0 + di))*4096 + l0 + lix];
        }
        for (int i = tid; i < 40*16; i += 256) {
            int j = i / 16, kk = i % 16;
            ws[j][kk] = x_w[j*256 + k0 + kk];
        }
        __syncthreads();
        #pragma unroll
        for (int di = 0; di < 16; di++) {
            float a = xs[di][ll];
            #pragma unroll
            for (int jj = 0; jj < 20; jj++)
                acc[jj] = fmaf(a, ws[jg*20 + jj][di], acc[jj]);
        }
        __syncthreads();
    }
    int l = l0 + ll;
    #pragma unroll
    for (int jj = 0; jj < 20; jj++) {
        int j = jg*20 + jj;
        float v = acc[jj];
        if (j < 8)       g_dtr[((size_t)b*4096 + l)*8  + j]       = v;
        else if (j < 24) g_Bm [((size_t)b*4096 + l)*16 + (j - 8)] = v;
        else             g_Cm [((size_t)b*4096 + l)*16 + (j - 24)] = v;
    }
}

// ---------------- K4: dt = softplus(dtr @ dt_w^T + dt_b), layout (b,d,l) ----------------
__global__ void dtproj_kernel(const float* __restrict__ dt_w, const float* __restrict__ dt_b) {
    int bid = blockIdx.x;             // 4*256*16
    int lc = bid & 15;
    int d  = (bid >> 4) & 255;
    int b  = bid >> 12;
    int l0 = lc * 256;
    __shared__ float s[8][264];
    for (int i = threadIdx.x; i < 2048; i += 256) {
        float v = g_dtr[((size_t)b*4096 + l0)*8 + i];
        s[i & 7][i >> 3] = v;
    }
    __syncthreads();
    float acc = dt_b[d];
    #pragma unroll
    for (int r = 0; r < 8; r++) acc = fmaf(s[r][threadIdx.x], dt_w[d*8 + r], acc);
    g_dt[((size_t)(b*256 + d))*4096 + l0 + threadIdx.x] = softplus_f(acc);
}

// ---------------- K5a: scan pass A — per-segment decay product + end state ----------------
__global__ void scanA_kernel(const float* __restrict__ A_log) {
    // grid 1024 x 256: 16 half-warp tasks per block; task = (chain, segment)
    int tid = threadIdx.x;
    int n = tid & 15;
    int task = blockIdx.x * 16 + (tid >> 4);   // 0..16383
    int chain = task >> 4;                     // b*256+d
    int s = task & 15;
    int b = chain >> 8, d = chain & 255;
    int l0 = s * SEGL;
    const float* dtp = g_dt + (size_t)chain*4096 + l0;
    const float* xp  = g_x  + (size_t)chain*4096 + l0;
    const float* Bp  = g_Bm + ((size_t)b*4096 + l0)*16 + n;
    float An = -__expf(A_log[d*16 + n]);
    float h = 0.f, P = 1.f;
    for (int l = 0; l < SEGL; l += 4) {
        float4 dt4 = *(const float4*)(dtp + l);
        float4 x4  = *(const float4*)(xp  + l);
        float dta[4] = {dt4.x, dt4.y, dt4.z, dt4.w};
        float xa [4] = {x4.x,  x4.y,  x4.z,  x4.w};
        #pragma unroll
        for (int i = 0; i < 4; i++) {
            float dt = dta[i];
            float Bv = Bp[(l + i)*16];
            float dA = __expf(dt * An);
            P *= dA;
            h = fmaf(dA, h, dt * xa[i] * Bv);
        }
    }
    g_segH[task*16 + n] = h;
    g_segP[task*16 + n] = P;
}

// ---------------- K5b: combine — prefix over segments per (chain, n) ----------------
__global__ void scanC_kernel() {
    int t = blockIdx.x * 256 + threadIdx.x;    // 16384 = 1024 chains * 16 n
    int chain = t >> 4, n = t & 15;
    float h = 0.f;
    #pragma unroll
    for (int s = 0; s < NSEG; s++) {
        int idx = (chain*16 + s)*16 + n;
        g_h0[idx] = h;
        h = g_segH[idx] + g_segP[idx]*h;
    }
}

// ---------------- K5c: scan pass B — outputs, y in (b,d,l) layout ----------------
__global__ void scanB_kernel(const float* __restrict__ A_log, const float* __restrict__ Dp) {
    int tid = threadIdx.x;
    int n = tid & 15;
    int task = blockIdx.x * 16 + (tid >> 4);
    int chain = task >> 4;
    int s = task & 15;
    int b = chain >> 8, d = chain & 255;
    int l0 = s * SEGL;
    const float* dtp = g_dt + (size_t)chain*4096 + l0;
    const float* xp  = g_x  + (size_t)chain*4096 + l0;
    const float* zp  = g_z  + (size_t)chain*4096 + l0;
    const float* Bp  = g_Bm + ((size_t)b*4096 + l0)*16 + n;
    const float* Cp  = g_Cm + ((size_t)b*4096 + l0)*16 + n;
    float* yout = g_y + (size_t)chain*4096 + l0;
    float An = -__expf(A_log[d*16 + n]);
    float Dd = Dp[d];
    float h = g_h0[task*16 + n];
    for (int l = 0; l < SEGL; l += 4) {
        float4 dt4 = *(const float4*)(dtp + l);
        float4 x4  = *(const float4*)(xp  + l);
        float4 z4  = *(const float4*)(zp  + l);
        float dta[4] = {dt4.x, dt4.y, dt4.z, dt4.w};
        float xa [4] = {x4.x,  x4.y,  x4.z,  x4.w};
        float za [4] = {z4.x,  z4.y,  z4.z,  z4.w};
        float ov[4];
        #pragma unroll
        for (int i = 0; i < 4; i++) {
            float dt = dta[i];
            float Bv = Bp[(l + i)*16];
            float Cv = Cp[(l + i)*16];
            float dA = __expf(dt * An);
            h = fmaf(dA, h, dt * xa[i] * Bv);
            float y = h * Cv;
            y += __shfl_xor_sync(0xFFFFFFFFu, y, 8);
            y += __shfl_xor_sync(0xFFFFFFFFu, y, 4);
            y += __shfl_xor_sync(0xFFFFFFFFu, y, 2);
            y += __shfl_xor_sync(0xFFFFFFFFu, y, 1);
            float zz = za[i];
            float gate = zz / (1.f + __expf(-zz));
            ov[i] = fmaf(xa[i], Dd, y) * gate;
        }
        if (n == 0) {
            float4 o4 = make_float4(ov[0], ov[1], ov[2], ov[3]);
            *(float4*)(yout + l) = o4;
        }
    }
}

// ---------------- K6: collapse out_w group-sum ----------------
__global__ void wsum_kernel(const float* __restrict__ out_w) {
    int i = blockIdx.x * 256 + threadIdx.x;  // 8192
    int c = i >> 8, d = i & 255;
    g_wsum[c*256 + d] = out_w[(c)*256 + d] + out_w[(32 + c)*256 + d]
                      + out_w[(64 + c)*256 + d] + out_w[(96 + c)*256 + d];
}

// ---------------- K7: res_seq[b,l,c] = sum_d y[b,d,l] * wsum[c,d]  (A transposed) ----------------
__global__ void gemm3t_kernel() {
    int b = blockIdx.x >> 5, lt = blockIdx.x & 31;
    int l0 = lt * 128;
    __shared__ float xs[16][128];
    __shared__ float ws[32][17];
    int tid = threadIdx.x;
    int ll = tid & 127, jg = tid >> 7;     // 2 groups x 16 c
    float acc[16];
    #pragma unroll
    for (int j = 0; j < 16; j++) acc[j] = 0.f;

    for (int k0 = 0; k0 < 256; k0 += 16) {
        for (int i = tid; i < 16*128; i += 256) {
            int di = i >> 7, lix = i & 127;
            xs[di][lix] = g_y[((size_t)(b*256 + k0 + di))*4096 + l0 + lix];
        }
        for (int i = tid; i < 32*16; i += 256) {
            int j = i / 16, kk = i % 16;
            ws[j][kk] = g_wsum[j*256 + k0 + kk];
        }
        __syncthreads();
        #pragma unroll
        for (int di = 0; di < 16; di++) {
            float a = xs[di][ll];
            #pragma unroll
            for (int jj = 0; jj < 16; jj++)
                acc[jj] = fmaf(a, ws[jg*16 + jj][di], acc[jj]);
        }
        __syncthreads();
    }
    int l = l0 + ll;
    #pragma unroll
    for (int jj = 0; jj < 16; jj++)
        g_res_seq[((size_t)b*4096 + l)*32 + jg*16 + jj] = acc[jj];
}

// ---------------- K8: residual = res_seq^T * fo2, per-(b,c) sum ----------------
__global__ void residual_kernel(const float* __restrict__ fo2) {
    int b = blockIdx.x >> 5, c = blockIdx.x & 31;
    float partial = 0.f;
    for (int l = threadIdx.x; l < 4096; l += 256) {
        float r = g_res_seq[((size_t)b*4096 + l)*32 + c] * fo2[((size_t)(b*32 + c))*4096 + l];
        g_residual[((size_t)(b*32 + c))*4096 + l] = r;
        partial += r;
    }
    __shared__ float red[256];
    red[threadIdx.x] = partial;
    __syncthreads();
    for (int st = 128; st > 0; st >>= 1) {
        if (threadIdx.x < st) red[threadIdx.x] += red[threadIdx.x + st];
        __syncthreads();
    }
    if (threadIdx.x == 0) g_cmean[b*32 + c] = red[0];
}

// ---------------- K9: entire tiny mamba2, one block ----------------
__global__ void mamba2_kernel(const float* __restrict__ in_w, const float* __restrict__ conv_w,
                              const float* __restrict__ conv_b, const float* __restrict__ x_w,
                              const float* __restrict__ dt_w, const float* __restrict__ dt_b,
                              const float* __restrict__ A_log, const float* __restrict__ Dp,
                              const float* __restrict__ out_w) {
    __shared__ float sxp[4][32][4];
    __shared__ float sx [4][32][4];
    __shared__ float sz [4][32][4];
    __shared__ float sdt[4][32][4];
    __shared__ float sB [4][32][16];
    __shared__ float sC [4][32][16];
    __shared__ float sy [4][32][4];
    int tid = threadIdx.x;            // 128
    int b = tid >> 5, l = tid & 31;
    float m0 = g_cmean[b*32 + l] * (1.f/4096.f);
    float m1 = g_cmean[b*32 + 31 - l] * (1.f/4096.f);
    #pragma unroll
    for (int j = 0; j < 4; j++) {
        sxp[b][l][j] = m0*in_w[j*2]       + m1*in_w[j*2 + 1];
        sz [b][l][j] = m0*in_w[(j+4)*2]   + m1*in_w[(j+4)*2 + 1];
    }
    __syncthreads();
    #pragma unroll
    for (int c = 0; c < 4; c++) {
        float acc = conv_b[c];
        #pragma unroll
        for (int t = 0; t < 4; t++) {
            int ls = l - 3 + t;
            float v = (ls >= 0) ? sxp[b][ls][c] : 0.f;
            acc = fmaf(conv_w[c*4 + t], v, acc);
        }
        sx[b][l][c] = acc / (1.f + expf(-acc));
    }
    __syncthreads();
    {
        float xv[4] = {sx[b][l][0], sx[b][l][1], sx[b][l][2], sx[b][l][3]};
        float dtr = 0.f;
        #pragma unroll
        for (int c = 0; c < 4; c++) dtr = fmaf(xv[c], x_w[c], dtr);
        #pragma unroll
        for (int n = 0; n < 16; n++) {
            float bb = 0.f, cc = 0.f;
            #pragma unroll
            for (int c = 0; c < 4; c++) {
                bb = fmaf(xv[c], x_w[(1 + n)*4 + c], bb);
                cc = fmaf(xv[c], x_w[(17 + n)*4 + c], cc);
            }
            sB[b][l][n] = bb;
            sC[b][l][n] = cc;
        }
        #pragma unroll
        for (int dd = 0; dd < 4; dd++) {
            float a = fmaf(dtr, dt_w[dd], dt_b[dd]);
            sdt[b][l][dd] = softplus_f(a);
        }
    }
    __syncthreads();
    {
        int lane = tid & 31, wb = tid >> 5;
        int grp = lane >> 4, n = lane & 15;
        int d0 = grp, d1 = grp + 2;
        float A0 = -expf(A_log[d0*16 + n]);
        float A1 = -expf(A_log[d1*16 + n]);
        float h0 = 0.f, h1 = 0.f;
        for (int t = 0; t < 32; t++) {
            float Bv = sB[wb][t][n], Cv = sC[wb][t][n];
            float dt0 = sdt[wb][t][d0], x0 = sx[wb][t][d0];
            float dt1 = sdt[wb][t][d1], x1 = sx[wb][t][d1];
            h0 = fmaf(__expf(dt0*A0), h0, dt0*x0*Bv);
            h1 = fmaf(__expf(dt1*A1), h1, dt1*x1*Bv);
            float y0 = h0*Cv, y1 = h1*Cv;
            y0 += __shfl_xor_sync(0xFFFFFFFFu, y0, 8);
            y0 += __shfl_xor_sync(0xFFFFFFFFu, y0, 4);
            y0 += __shfl_xor_sync(0xFFFFFFFFu, y0, 2);
            y0 += __shfl_xor_sync(0xFFFFFFFFu, y0, 1);
            y1 += __shfl_xor_sync(0xFFFFFFFFu, y1, 8);
            y1 += __shfl_xor_sync(0xFFFFFFFFu, y1, 4);
            y1 += __shfl_xor_sync(0xFFFFFFFFu, y1, 2);
            y1 += __shfl_xor_sync(0xFFFFFFFFu, y1, 1);
            if (n == 0) { sy[wb][t][d0] = y0; sy[wb][t][d1] = y1; }
        }
    }
    __syncthreads();
    {
        float scale = 0.f;
        #pragma unroll
        for (int dd = 0; dd < 4; dd++) {
            float yv = fmaf(sx[b][l][dd], Dp[dd], sy[b][l][dd]);
            float zz = sz[b][l][dd];
            yv *= zz / (1.f + expf(-zz));
            scale = fmaf(yv, out_w[dd] + out_w[4 + dd], scale);
        }
        g_scale[b*32 + l] = scale;
    }
}

// ---------------- K10: out = residual * (scale + 1) ----------------
__global__ void final_kernel(float* __restrict__ out) {
    int idx = blockIdx.x * 256 + threadIdx.x;  // 524288
    out[idx] = g_residual[idx] * (g_scale[idx >> 12] + 1.f);
}

// ---------------- launch ----------------
extern "C" void kernel_launch(void* const* d_in, const int* in_sizes, int n_in,
                              void* d_out, int out_size) {
    const float* fo1      = (const float*)d_in[0];
    const float* fo2      = (const float*)d_in[1];
    const float* m1_in_w  = (const float*)d_in[2];
    const float* m1_conv_w= (const float*)d_in[3];
    const float* m1_conv_b= (const float*)d_in[4];
    const float* m1_x_w   = (const float*)d_in[5];
    const float* m1_dt_w  = (const float*)d_in[6];
    const float* m1_dt_b  = (const float*)d_in[7];
    const float* m1_A_log = (const float*)d_in[8];
    const float* m1_D     = (const float*)d_in[9];
    const float* m1_out_w = (const float*)d_in[10];
    const float* m2_in_w  = (const float*)d_in[11];
    const float* m2_conv_w= (const float*)d_in[12];
    const float* m2_conv_b= (const float*)d_in[13];
    const float* m2_x_w   = (const float*)d_in[14];
    const float* m2_dt_w  = (const float*)d_in[15];
    const float* m2_dt_b  = (const float*)d_in[16];
    const float* m2_A_log = (const float*)d_in[17];
    const float* m2_D     = (const float*)d_in[18];
    const float* m2_out_w = (const float*)d_in[19];
    float* out = (float*)d_out;

    gather_kernel<<<8192, 256>>>(fo1);
    gemm1_kernel<<<dim3(512/64, 16384/128), 256>>>(m1_in_w);
    conv_transpose_kernel<<<dim3(16, 128, 4), 256>>>(m1_conv_w, m1_conv_b);
    gemm2_kernel<<<128, 256>>>(m1_x_w);
    dtproj_kernel<<<4*256*16, 256>>>(m1_dt_w, m1_dt_b);
    // chunked selective scan
    scanA_kernel<<<1024, 256>>>(m1_A_log);
    scanC_kernel<<<64, 256>>>();
    scanB_kernel<<<1024, 256>>>(m1_A_log, m1_D);
    // group-summed out projection (y transposed)
    wsum_kernel<<<32, 256>>>(m1_out_w);
    gemm3t_kernel<<<128, 256>>>();
    residual_kernel<<<128, 256>>>(fo2);
    mamba2_kernel<<<1, 128>>>(m2_in_w, m2_conv_w, m2_conv_b, m2_x_w, m2_dt_w,
                              m2_dt_b, m2_A_log, m2_D, m2_out_w);
    final_kernel<<<2048, 256>>>(out);
}